// round 16
// baseline (speedup 1.0000x reference)
#include <cuda_runtime.h>

// GlobalFilter: y = irfft2(rfft2(x, ortho) * W, ortho), 14x14 spatial, B=256, C=512.
// R16: R15 + pairwise tree reduction of all DC/Nyquist accumulation chains
//      (depth 7 -> 3 in stages A / B-forward / B-inverse; stage A' v0/v7
//      factored as base + n2 * tree-sum(+-rr)). Pure dependency-shortening;
//      op counts equal or lower.

#define NC 32
#define NTHR 256

typedef unsigned long long u64;

__device__ __forceinline__ u64 pk2(float x, float y) {
    u64 r; asm("mov.b64 %0, {%1, %2};" : "=l"(r) : "f"(x), "f"(y)); return r;
}
__device__ __forceinline__ void upk2(u64 v, float& x, float& y) {
    asm("mov.b64 {%0, %1}, %2;" : "=f"(x), "=f"(y) : "l"(v));
}
__device__ __forceinline__ u64 f2fma(u64 a, u64 b, u64 c) {
    u64 d; asm("fma.rn.f32x2 %0, %1, %2, %3;" : "=l"(d) : "l"(a), "l"(b), "l"(c)); return d;
}
__device__ __forceinline__ u64 f2add(u64 a, u64 b) {
    u64 d; asm("add.rn.f32x2 %0, %1, %2;" : "=l"(d) : "l"(a), "l"(b)); return d;
}
__device__ __forceinline__ u64 f2sub(u64 a, u64 b) {
    u64 d; asm("sub.rn.f32x2 %0, %1, %2;" : "=l"(d) : "l"(a), "l"(b)); return d;
}
__device__ __forceinline__ u64 f2mul(u64 a, u64 b) {
    u64 d; asm("mul.rn.f32x2 %0, %1, %2;" : "=l"(d) : "l"(a), "l"(b)); return d;
}

// tree-sum of v[1..6] plus base: depth 3
__device__ __forceinline__ u64 tsum6(u64 base, const u64* v) {
    u64 p01 = f2add(v[1], v[2]);
    u64 p23 = f2add(v[3], v[4]);
    u64 p45 = f2add(v[5], v[6]);
    return f2add(f2add(base, p01), f2add(p23, p45));
}
// alternating tree-sum: base - v1 + v2 - v3 + v4 - v5 + v6: depth 3
__device__ __forceinline__ u64 tsalt6(u64 base, const u64* v) {
    u64 m01 = f2sub(v[2], v[1]);
    u64 m23 = f2sub(v[4], v[3]);
    u64 m45 = f2sub(v[6], v[5]);
    return f2add(f2add(base, m01), f2add(m23, m45));
}

__global__ __launch_bounds__(NTHR, 4) void gf_kernel(const float* __restrict__ x,
                                                     const float* __restrict__ w,
                                                     float* __restrict__ y) {
    __shared__ u64 E[14 * 8 * NC];   // interleaved complex (re, im) per channel, 28672 B

    const int b  = blockIdx.y;
    const int c0 = blockIdx.x * NC;
    const int tid = threadIdx.x;

    const float CC[14] = {
         1.0000000000000000f,  0.9009688679024191f,  0.6234898018587336f,
         0.2225209339563144f, -0.2225209339563143f, -0.6234898018587335f,
        -0.9009688679024191f, -1.0000000000000000f, -0.9009688679024191f,
        -0.6234898018587336f, -0.2225209339563146f,  0.2225209339563143f,
         0.6234898018587334f,  0.9009688679024190f
    };
    const float SS[14] = {
         0.0000000000000000f,  0.4338837391175581f,  0.7818314824680298f,
         0.9749279121818236f,  0.9749279121818236f,  0.7818314824680299f,
         0.4338837391175582f,  0.0000000000000000f, -0.4338837391175581f,
        -0.7818314824680297f, -0.9749279121818236f, -0.9749279121818238f,
        -0.7818314824680300f, -0.4338837391175583f
    };

    // ---- Stage A: rfft along q. 224 pair-tasks (2 channels each). ----
    if (tid < 224) {
        const int cp = (tid & 15) << 1;      // even channel within tile
        const int p  = tid >> 4;             // 0..13
        const float2* xp = reinterpret_cast<const float2*>(
            x + ((b * 196) + p * 14) * 512 + c0 + cp);

        u64 r[14];                           // lanes = (c0, c1)
        #pragma unroll
        for (int q = 0; q < 14; q++) {
            float2 t = xp[q * 256];
            r[q] = pk2(t.x, t.y);
        }
        u64 s[7], dd[7];
        #pragma unroll
        for (int j = 1; j <= 6; j++) {
            s[j]  = f2add(r[j], r[14 - j]);
            dd[j] = f2sub(r[j], r[14 - j]);
        }
        const u64 bs = f2add(r[0], r[7]);
        const u64 bd = f2sub(r[0], r[7]);
        {
            u64 e0 = tsum6(bs, s);           // depth-3 trees
            u64 e7 = tsalt6(bd, s);
            float a0, a1, b0, b1;
            upk2(e0, a0, a1); upk2(e7, b0, b1);
            reinterpret_cast<float4*>(E + (p * 8 + 0) * NC + cp)[0] =
                make_float4(a0, 0.0f, a1, 0.0f);
            reinterpret_cast<float4*>(E + (p * 8 + 7) * NC + cp)[0] =
                make_float4(b0, 0.0f, b1, 0.0f);
        }
        #pragma unroll
        for (int k2 = 1; k2 <= 6; k2++) {
            u64 er = (k2 & 1) ? bd : bs;
            u64 ei = f2mul(dd[1], pk2(-SS[k2 % 14], -SS[k2 % 14]));
            er = f2fma(s[1], pk2(CC[k2 % 14], CC[k2 % 14]), er);
            #pragma unroll
            for (int j = 2; j <= 6; j++) {
                const int m = (k2 * j) % 14;
                er = f2fma(s[j],  pk2(CC[m], CC[m]), er);
                ei = f2fma(dd[j], pk2(-SS[m], -SS[m]), ei);
            }
            float er0, er1, ei0, ei1;
            upk2(er, er0, er1); upk2(ei, ei0, ei1);
            reinterpret_cast<float4*>(E + (p * 8 + k2) * NC + cp)[0] =
                make_float4(er0, ei0, er1, ei1);
        }
    }
    __syncthreads();

    // ---- Stage B: fft over p, * W (raw), ifft over p; z folded to s2/d2
    //      inside the pair loop. 1 task/thread. ----
    {
        const int c  = tid & (NC - 1);
        const int k2 = tid >> 5;
        u64* col = E + k2 * NC + c;          // element (p) at col[p * 8*NC]
        const int PS = 8 * NC;               // 256

        const u64 e0 = col[0];
        const u64 e7 = col[7 * PS];
        u64 s[7], d[7];
        #pragma unroll
        for (int j = 1; j <= 6; j++) {
            u64 a = col[j * PS], bb = col[(14 - j) * PS];
            s[j] = f2add(a, bb);
            d[j] = f2sub(a, bb);
        }

        const float2* wp = reinterpret_cast<const float2*>(w) + k2 * 512 + c0 + c;

        const u64 bp = f2add(e0, e7);
        const u64 bm = f2sub(e0, e7);

        u64 z0, z7;                          // weighted DC / Nyquist
        {
            const float2 wv0 = wp[0];
            const float2 wv7 = wp[7 * 8 * 512];
            u64 a0 = tsum6(bp, s);           // depth-3 trees
            u64 a7 = tsalt6(bm, s);
            float zr, zi;
            upk2(a0, zr, zi);
            z0 = pk2(zr * wv0.x - zi * wv0.y, zr * wv0.y + zi * wv0.x);
            upk2(a7, zr, zi);
            z7 = pk2(zr * wv7.x - zi * wv7.y, zr * wv7.y + zi * wv7.x);
        }

        u64 s2[7], d2[7];                    // folded weighted pairs
        #pragma unroll
        for (int k1 = 1; k1 <= 6; k1++) {
            const float2 wvA = wp[k1 * 8 * 512];
            const float2 wvB = wp[(14 - k1) * 8 * 512];
            u64 AC = f2mul(s[1], pk2(CC[k1 % 14], CC[k1 % 14]));
            u64 DB = f2mul(d[1], pk2(SS[k1 % 14], SS[k1 % 14]));
            #pragma unroll
            for (int j = 2; j <= 6; j++) {
                const int m = (k1 * j) % 14;
                AC = f2fma(s[j], pk2(CC[m], CC[m]), AC);
                DB = f2fma(d[j], pk2(SS[m], SS[m]), DB);
            }
            float A, C, D, Bv, bR, bI;
            upk2(AC, A, C); upk2(DB, D, Bv);
            upk2((k1 & 1) ? bm : bp, bR, bI);
            const float zra = bR + A + Bv, zia = bI + C - D;     // Z[k1]
            const float zrb = bR + A - Bv, zib = bI + C + D;     // Z[14-k1]
            const float zAr = zra * wvA.x - zia * wvA.y, zAi = zra * wvA.y + zia * wvA.x;
            const float zBr = zrb * wvB.x - zib * wvB.y, zBi = zrb * wvB.y + zib * wvB.x;
            s2[k1] = pk2(zAr + zBr, zAi + zBi);   // z never stored
            d2[k1] = pk2(zAr - zBr, zAi - zBi);
        }

        // inverse fft over p (e^{+i theta}) from z0, z7, s2, d2
        const u64 zp = f2add(z0, z7);
        const u64 zm = f2sub(z0, z7);
        {
            u64 o0 = tsum6(zp, s2);          // depth-3 trees
            u64 o7 = tsalt6(zm, s2);
            col[0]      = o0;
            col[7 * PS] = o7;
        }
        #pragma unroll
        for (int p = 1; p <= 6; p++) {
            u64 AC = f2mul(s2[1], pk2(CC[p % 14], CC[p % 14]));
            u64 DB = f2mul(d2[1], pk2(SS[p % 14], SS[p % 14]));
            #pragma unroll
            for (int j = 2; j <= 6; j++) {
                const int m = (p * j) % 14;
                AC = f2fma(s2[j], pk2(CC[m], CC[m]), AC);
                DB = f2fma(d2[j], pk2(SS[m], SS[m]), DB);
            }
            float A, C, D, Bv, bR, bI;
            upk2(AC, A, C); upk2(DB, D, Bv);
            upk2((p & 1) ? zm : zp, bR, bI);
            col[p * PS]        = pk2(bR + A - Bv, bI + C + D);
            col[(14 - p) * PS] = pk2(bR + A + Bv, bI + C - D);
        }
    }
    __syncthreads();

    // ---- Stage A': irfft along q; 1/196 folded into constants.
    //      224 pair-tasks (2 channels each). ----
    if (tid < 224) {
        const int cp = (tid & 15) << 1;
        const int p  = tid >> 4;
        const float4* row = reinterpret_cast<const float4*>(E + (p * 8) * NC + cp);

        const float inv196 = 1.0f / 196.0f;
        const float n2 = 2.0f / 196.0f;

        u64 ea[8], eb[8];
        u64 rr[8];
        #pragma unroll
        for (int k2 = 0; k2 < 8; k2++) {
            float4 t = row[k2 * (NC / 2)];
            ea[k2] = pk2(t.x, t.y);
            eb[k2] = pk2(t.z, t.w);
            rr[k2] = pk2(t.x, t.z);
        }

        float2* yout = reinterpret_cast<float2*>(
            y + ((b * 196) + p * 14) * 512 + c0 + cp);

        const u64 nrm    = pk2(inv196, inv196);
        const u64 base_e = f2mul(f2add(rr[0], rr[7]), nrm);
        const u64 base_o = f2mul(f2sub(rr[0], rr[7]), nrm);
        {
            // v0 = base_e + n2 * tree-sum(rr[1..6]); v7 alternating
            u64 srr = f2add(f2add(rr[1], rr[2]),
                            f2add(f2add(rr[3], rr[4]), f2add(rr[5], rr[6])));
            u64 arr = f2add(f2sub(rr[2], rr[1]),
                            f2add(f2sub(rr[4], rr[3]), f2sub(rr[6], rr[5])));
            u64 v0 = f2fma(srr, pk2(n2, n2), base_e);
            u64 v7 = f2fma(arr, pk2(n2, n2), base_o);
            float v00, v01, v70, v71;
            upk2(v0, v00, v01); upk2(v7, v70, v71);
            yout[0]       = make_float2(v00, v01);
            yout[7 * 256] = make_float2(v70, v71);
        }
        #pragma unroll
        for (int q = 1; q <= 6; q++) {
            u64 AB0 = f2mul(ea[1], pk2(n2 * CC[q % 14], n2 * SS[q % 14]));
            u64 AB1 = f2mul(eb[1], pk2(n2 * CC[q % 14], n2 * SS[q % 14]));
            #pragma unroll
            for (int k2 = 2; k2 <= 6; k2++) {
                const int m = (k2 * q) % 14;
                const u64 tw = pk2(n2 * CC[m], n2 * SS[m]);
                AB0 = f2fma(ea[k2], tw, AB0);
                AB1 = f2fma(eb[k2], tw, AB1);
            }
            float A0, B0, A1, B1, bc0, bc1;
            upk2(AB0, A0, B0); upk2(AB1, A1, B1);
            upk2((q & 1) ? base_o : base_e, bc0, bc1);
            yout[q * 256]        = make_float2(bc0 + A0 - B0, bc1 + A1 - B1);
            yout[(14 - q) * 256] = make_float2(bc0 + A0 + B0, bc1 + A1 + B1);
        }
    }
}

extern "C" void kernel_launch(void* const* d_in, const int* in_sizes, int n_in,
                              void* d_out, int out_size) {
    const float* x = (const float*)d_in[0];        // [256,196,512] f32
    const float* w = (const float*)d_in[1];        // [14,8,512,2]  f32
    float* y = (float*)d_out;                      // [256,196,512] f32

    dim3 grid(512 / NC, 256);                      // 16 x 256 = 4096 CTAs
    gf_kernel<<<grid, NTHR>>>(x, w, y);
}